// round 11
// baseline (speedup 1.0000x reference)
#include <cuda_runtime.h>
#include <cuda_bf16.h>

#define DIMC 64
#define HID  170
#define HW   256
#define HWHW (HW * HW)

// sh layout: row stride 38 (conflict-free rows), double-buffered
#define SH_RS  38
#define SH_CH  380        // 10 * 38
#define SH_GRP 760        // 2 ch * 380
#define SH_BUF 3800       // 5 groups * SH_GRP
// sG layout: XOR-swizzled rows of 256 words, double-buffered
#define SG_RS  256
#define SG_BUF 2560       // 10 ch * SG_RS

// h scratch: [4][170][256][256] f32 = 178 MB (static __device__ => allocation-free)
__device__ float g_h[(size_t)4 * HID * HW * HW];

// Packed dual-FMA (Blackwell f32x2 pipe): d = a*b + c on 2 floats per instr.
__device__ __forceinline__ float2 ffma2(float2 a, float2 b, float2 c) {
    float2 d;
    asm("fma.rn.f32x2 %0, %1, %2, %3;"
        : "=l"(reinterpret_cast<unsigned long long&>(d))
        : "l"(reinterpret_cast<const unsigned long long&>(a)),
          "l"(reinterpret_cast<const unsigned long long&>(b)),
          "l"(reinterpret_cast<const unsigned long long&>(c)));
    return d;
}

__device__ __forceinline__ float f4c(const float4& v, int kk) {
    return (kk == 0) ? v.x : (kk == 1) ? v.y : (kk == 2) ? v.z : v.w;
}

// tanh-approx GELU (matches exact GELU to ~1e-6 rel in our small-|x| regime)
__device__ __forceinline__ float gelu_t(float x) {
    float u = 0.7978845608f * x * (1.f + 0.044715f * x * x);
    float t;
    asm("tanh.approx.f32 %0, %1;" : "=f"(t) : "f"(u));
    return 0.5f * x * (1.f + t);
}

// XOR swizzle on float4 blocks: injective, conflict-free for our access shapes.
__device__ __forceinline__ int sg_addr4(int blk) {
    return 4 * (blk ^ ((blk >> 3) & 7));
}

// ---------------------------------------------------------------------------
// Pass 1: 1x1 conv (64 -> 170) + 2x2 patch spectral filter (4x4 Hadamard map)
// grid (2, 128, 4). block 256. (unchanged — proven ~138us)
// ---------------------------------------------------------------------------
extern "C" __global__ void __launch_bounds__(256, 2)
pass1_kernel(const float* __restrict__ x, const float* __restrict__ W_in,
             const float* __restrict__ fftf)
{
    extern __shared__ float smem[];
    float* sx = smem;               // [64][256] patch-grouped: sx[k*256 + 4*P + s]
    float* sF = sx + 64 * 256;      // [170][4]

    const int tid = threadIdx.x;
    const int b   = blockIdx.z;
    const int py  = blockIdx.y;
    const int c0b = blockIdx.x * 128;

    for (int i = tid; i < HID * 4; i += 256) sF[i] = fftf[i];

    const float* xb = x + (size_t)b * 64 * HWHW;
    for (int idx = tid; idx < 4096; idx += 256) {
        int k  = idx >> 6;
        int r  = (idx >> 5) & 1;
        int c4 = idx & 31;
        float4 v = *(const float4*)(xb + ((size_t)k * HW + 2 * py + r) * HW + c0b + 4 * c4);
        int base = k * 256 + 8 * c4 + 2 * r;
        *(float2*)(sx + base)     = make_float2(v.x, v.y);
        *(float2*)(sx + base + 4) = make_float2(v.z, v.w);
    }
    __syncthreads();

    const int j  = tid & 31;   // patch slots j, j+32
    const int is = tid >> 5;   // channel octet slot (warp id)

    #pragma unroll
    for (int cb = 0; cb < 192; cb += 64) {
        const int cbase = cb + is * 8;
        if (cbase >= HID) continue;

        float2 acc[8][2][2];
        #pragma unroll
        for (int cc = 0; cc < 8; cc++)
            #pragma unroll
            for (int p = 0; p < 2; p++)
                acc[cc][p][0] = acc[cc][p][1] = make_float2(0.f, 0.f);

        const float4* wbase = (const float4*)W_in;
        #pragma unroll
        for (int k4 = 0; k4 < 16; k4++) {
            float4 w[8];
            #pragma unroll
            for (int cc = 0; cc < 8; cc++) {
                int c = cbase + cc;
                w[cc] = __ldg(wbase + (c < HID ? c : 0) * 16 + k4);
            }
            #pragma unroll
            for (int kk = 0; kk < 4; kk++) {
                const float* row = sx + (k4 * 4 + kk) * 256;
                float4 v0 = *(const float4*)(row + 4 * j);
                float4 v1 = *(const float4*)(row + 4 * (j + 32));
                float2 v0lo = make_float2(v0.x, v0.y), v0hi = make_float2(v0.z, v0.w);
                float2 v1lo = make_float2(v1.x, v1.y), v1hi = make_float2(v1.z, v1.w);
                #pragma unroll
                for (int cc = 0; cc < 8; cc++) {
                    float ws = f4c(w[cc], kk);
                    float2 w2 = make_float2(ws, ws);
                    acc[cc][0][0] = ffma2(w2, v0lo, acc[cc][0][0]);
                    acc[cc][0][1] = ffma2(w2, v0hi, acc[cc][0][1]);
                    acc[cc][1][0] = ffma2(w2, v1lo, acc[cc][1][0]);
                    acc[cc][1][1] = ffma2(w2, v1hi, acc[cc][1][1]);
                }
            }
        }

        #pragma unroll
        for (int cc = 0; cc < 8; cc++) {
            int c = cbase + cc;
            if (c >= HID) break;
            float f0 = sF[c * 4 + 0], f1 = sF[c * 4 + 1];
            float f2 = sF[c * 4 + 2], f3 = sF[c * 4 + 3];
            float* hb = g_h + (((size_t)b * HID + c) * HW + 2 * py) * HW + c0b;
            #pragma unroll
            for (int p = 0; p < 2; p++) {
                float a  = acc[cc][p][0].x, bb = acc[cc][p][0].y;
                float cv = acc[cc][p][1].x, dd = acc[cc][p][1].y;
                float X0 = a + bb + cv + dd;
                float X1 = a - bb + cv - dd;
                float X2 = a + bb - cv - dd;
                float X3 = a - bb - cv + dd;
                X0 *= 0.25f * f0; X1 *= 0.25f * f1; X2 *= 0.25f * f2; X3 *= 0.25f * f3;
                float o0 = X0 + X1 + X2 + X3;
                float o1 = X0 - X1 + X2 - X3;
                float o2 = X0 + X1 - X2 - X3;
                float o3 = X0 - X1 - X2 + X3;
                int P = j + 32 * p;
                *(float2*)(hb + 2 * P)      = make_float2(o0, o1);
                *(float2*)(hb + HW + 2 * P) = make_float2(o2, o3);
            }
        }
    }
}

// ---------------------------------------------------------------------------
// Pass 2: depthwise 3x3 + tanh-GELU gate + 1x1 (170->64).
// Software pipeline per chunk (ONE barrier):
//   [LDG(k+1) issue] -> phase A(k) -> STS(k+1) -> barrier -> phase B(k)
// so staging LDG latency hides under phase A math.
// Phase A: groups 0-3: 64 threads x 4 px; group 4: 256 threads x 1 px.
// Phase B: 16 outs x 4 px per thread.
// grid (8, 32, 4): pixel tile 32 wide x 8 tall. block 256.
// ---------------------------------------------------------------------------
extern "C" __global__ void __launch_bounds__(256, 2)
pass2_kernel(const float* __restrict__ W_dw, const float* __restrict__ W_out,
             float* __restrict__ out)
{
    extern __shared__ float smem[];
    float*  sWo  = smem;                          // [170][64] W_out^T
    float2* sDw1 = (float2*)(smem + HID * 64);    // [85][9] (Wdw[2g][t], Wdw[2g+1][t])
    float2* sDw2 = sDw1 + 85 * 9;                 // [85][9] (+170 bank)
    float*  sh   = (float*)(sDw2 + 85 * 9);       // [2 buf][5][2 ch][10][SH_RS]
    float*  sG   = sh + 2 * SH_BUF;               // [2 buf][10][SG_RS] swizzled

    const int tid = threadIdx.x;
    const int tx = tid & 31, ty = tid >> 5;
    const int b  = blockIdx.z;
    const int x0 = blockIdx.x * 32, y0 = blockIdx.y * 8;

    for (int idx = tid; idx < HID * 64; idx += 256) {
        int c = idx >> 6, o = idx & 63;
        sWo[idx] = W_out[o * HID + c];
    }
    for (int idx = tid; idx < 85 * 9; idx += 256) {
        int g = idx / 9, t = idx - 9 * g;
        sDw1[idx] = make_float2(W_dw[(2 * g) * 9 + t],       W_dw[(2 * g + 1) * 9 + t]);
        sDw2[idx] = make_float2(W_dw[(170 + 2 * g) * 9 + t], W_dw[(171 + 2 * g) * 9 + t]);
    }

    // Staging descriptors: 3 slots/thread covering 680 elements of one group-pair
    const float* gp[3];
    int  soff[3];
    bool sval[3];
    #pragma unroll
    for (int s = 0; s < 3; s++) {
        int idx = tid + 256 * s;
        bool act = idx < 680;
        int ii = act ? idx : 0;
        int ch  = ii >= 340;
        int rem = ii - ch * 340;
        int row = rem / 34, col = rem - row * 34;
        int gy = y0 - 1 + row, gx = x0 - 1 + col;
        bool inb = (gy >= 0) && (gy < HW) && (gx >= 0) && (gx < HW);
        sval[s] = act && inb;
        soff[s] = ch * SH_CH + row * SH_RS + col;
        gp[s] = g_h + (((size_t)b * HID + ch * 85) * HW + (inb ? gy : 0)) * HW + (inb ? gx : 0);
    }

    // phase-A mappings
    const int gi4 = tid >> 6;            // group 0..3 (4px path)
    const int t64 = tid & 63;
    const int ryA = t64 >> 3;            // 0..7
    const int cA  = (t64 & 7) * 4;       // col base 0..28
    const int ryS = tid >> 5;            // group-4 path: 1 px/thread
    const int pxS = tid & 31;
    const int wrA  = sg_addr4(ryA * 8 + (cA >> 2));
    const int wrS4 = sg_addr4((ryS * 32 + pxS) >> 2) + (pxS & 3);

    // phase-B mapping: 16 outs x 4 px
    const int obch = (ty & 3) * 16;      // out base
    const int ph   = ty >> 2;            // px half (0: px<128, 1: px>=128)
    const int rdG  = sg_addr4(ph * 32 + tx);

    float2 acc[16][2];
    #pragma unroll
    for (int o = 0; o < 16; o++) acc[o][0] = acc[o][1] = make_float2(0.f, 0.f);

    // ---- prologue: stage chunk 0 into sh buf 0 ----
    {
        float pf0[15];
        #pragma unroll
        for (int gi = 0; gi < 5; gi++)
            #pragma unroll
            for (int s = 0; s < 3; s++)
                pf0[gi * 3 + s] = sval[s] ? __ldg(gp[s] + (size_t)gi * HWHW) : 0.f;
        #pragma unroll
        for (int gi = 0; gi < 5; gi++) {
            float* dst = sh + gi * SH_GRP;
            dst[soff[0]] = pf0[gi * 3 + 0];
            dst[soff[1]] = pf0[gi * 3 + 1];
            if (tid < 680 - 512) dst[soff[2]] = pf0[gi * 3 + 2];
        }
    }
    __syncthreads();

    int buf = 0;
    for (int ck = 0; ck < 17; ck++) {
        float* shb = sh + buf * SH_BUF;
        float* sGb = sG + buf * SG_BUF;

        // ---- issue staging LDGs for chunk ck+1 FIRST (latency hides under A) ----
        float pf[15];
        if (ck < 16) {
            #pragma unroll
            for (int gi = 0; gi < 5; gi++) {
                size_t goff = (size_t)((ck + 1) * 5 + gi) * HWHW;
                #pragma unroll
                for (int s = 0; s < 3; s++)
                    pf[gi * 3 + s] = sval[s] ? __ldg(gp[s] + goff) : 0.f;
            }
        }

        // ---- phase A: dwconv + GELU gate -> sG[buf] ----
        // groups 0..3: 64 threads each, 4 px/thread
        {
            int g = ck * 5 + gi4;
            const float*  b0 = shb + gi4 * SH_GRP + ryA * SH_RS + cA;
            const float*  b1 = b0 + SH_CH;
            const float2* w1 = sDw1 + g * 9;
            const float2* w2 = sDw2 + g * 9;
            float2 a1[2][2], a2[2][2];
            #pragma unroll
            for (int u = 0; u < 2; u++)
                #pragma unroll
                for (int v = 0; v < 2; v++) {
                    a1[u][v] = make_float2(0.f, 0.f);
                    a2[u][v] = make_float2(0.f, 0.f);
                }
            #pragma unroll
            for (int r = 0; r < 3; r++) {
                float2 r0 = *(const float2*)(b0 + r * SH_RS);
                float2 r1 = *(const float2*)(b0 + r * SH_RS + 2);
                float2 r2 = *(const float2*)(b0 + r * SH_RS + 4);
                float2 q0 = *(const float2*)(b1 + r * SH_RS);
                float2 q1 = *(const float2*)(b1 + r * SH_RS + 2);
                float2 q2 = *(const float2*)(b1 + r * SH_RS + 4);
                float2 h01[3] = { r0, make_float2(r0.y, r1.x), r1 };
                float2 h23[3] = { r1, make_float2(r1.y, r2.x), r2 };
                float2 p01[3] = { q0, make_float2(q0.y, q1.x), q1 };
                float2 p23[3] = { q1, make_float2(q1.y, q2.x), q2 };
                #pragma unroll
                for (int kx = 0; kx < 3; kx++) {
                    float2 wa = w1[r * 3 + kx];
                    float2 wb = w2[r * 3 + kx];
                    a1[0][0] = ffma2(make_float2(wa.x, wa.x), h01[kx], a1[0][0]);
                    a1[0][1] = ffma2(make_float2(wa.x, wa.x), h23[kx], a1[0][1]);
                    a1[1][0] = ffma2(make_float2(wa.y, wa.y), h01[kx], a1[1][0]);
                    a1[1][1] = ffma2(make_float2(wa.y, wa.y), h23[kx], a1[1][1]);
                    a2[0][0] = ffma2(make_float2(wb.x, wb.x), p01[kx], a2[0][0]);
                    a2[0][1] = ffma2(make_float2(wb.x, wb.x), p23[kx], a2[0][1]);
                    a2[1][0] = ffma2(make_float2(wb.y, wb.y), p01[kx], a2[1][0]);
                    a2[1][1] = ffma2(make_float2(wb.y, wb.y), p23[kx], a2[1][1]);
                }
            }
            #pragma unroll
            for (int chn = 0; chn < 2; chn++) {
                float4 gv;
                gv.x = gelu_t(a1[chn][0].x) * a2[chn][0].x;
                gv.y = gelu_t(a1[chn][0].y) * a2[chn][0].y;
                gv.z = gelu_t(a1[chn][1].x) * a2[chn][1].x;
                gv.w = gelu_t(a1[chn][1].y) * a2[chn][1].y;
                *(float4*)(sGb + (2 * gi4 + chn) * SG_RS + wrA) = gv;
            }
        }
        // group 4: all 256 threads, 1 px/thread
        {
            int g = ck * 5 + 4;
            const float*  b0 = shb + 4 * SH_GRP + ryS * SH_RS + pxS;
            const float*  b1 = b0 + SH_CH;
            const float2* w1 = sDw1 + g * 9;
            const float2* w2 = sDw2 + g * 9;
            float2 x1p = make_float2(0.f, 0.f);
            float2 x2p = make_float2(0.f, 0.f);
            #pragma unroll
            for (int ky = 0; ky < 3; ky++) {
                #pragma unroll
                for (int kx = 0; kx < 3; kx++) {
                    float h0 = b0[ky * SH_RS + kx];
                    float h1 = b1[ky * SH_RS + kx];
                    x1p = ffma2(w1[ky * 3 + kx], make_float2(h0, h0), x1p);
                    x2p = ffma2(w2[ky * 3 + kx], make_float2(h1, h1), x2p);
                }
            }
            sGb[8 * SG_RS + wrS4] = gelu_t(x1p.x) * x2p.x;
            sGb[9 * SG_RS + wrS4] = gelu_t(x1p.y) * x2p.y;
        }

        // ---- STS staged chunk ck+1 into sh[buf^1] (loads already landed) ----
        if (ck < 16) {
            float* shn = sh + (buf ^ 1) * SH_BUF;
            #pragma unroll
            for (int gi = 0; gi < 5; gi++) {
                float* dst = shn + gi * SH_GRP;
                dst[soff[0]] = pf[gi * 3 + 0];
                dst[soff[1]] = pf[gi * 3 + 1];
                if (tid < 680 - 512) dst[soff[2]] = pf[gi * 3 + 2];
            }
        }
        __syncthreads();   // sG[buf] complete + sh[buf^1] complete

        // ---- phase B: GEMM accumulate (16 outs x 4 px per thread) ----
        #pragma unroll
        for (int kc = 0; kc < 10; kc++) {
            int c = ck * 10 + kc;
            const float4* wv = (const float4*)(sWo + c * 64 + obch);
            float4 w0 = wv[0], w1 = wv[1], w2v = wv[2], w3 = wv[3];
            float4 g = *(const float4*)(sGb + kc * SG_RS + rdG);
            float2 glo = make_float2(g.x, g.y);
            float2 ghi = make_float2(g.z, g.w);
            float ws[16] = {w0.x, w0.y, w0.z, w0.w, w1.x, w1.y, w1.z, w1.w,
                            w2v.x, w2v.y, w2v.z, w2v.w, w3.x, w3.y, w3.z, w3.w};
            #pragma unroll
            for (int o = 0; o < 16; o++) {
                float2 wp = make_float2(ws[o], ws[o]);
                acc[o][0] = ffma2(wp, glo, acc[o][0]);
                acc[o][1] = ffma2(wp, ghi, acc[o][1]);
            }
        }
        buf ^= 1;
        // Race audit: phaseA(k+1) writes sG[buf^1] while any warp still in
        // phaseB(k) reads sG[buf] (disjoint); STS(k+2) targets sh[buf] whose
        // last readers (phaseA(k)) all passed barrier(k); sh[buf^1] reads in
        // phaseA(k+1) fenced by barrier(k).
    }

    // ---- store: thread owns outs [obch, obch+16) at 4 px ----
    const int srow = ph * 4 + (tx >> 3);
    const int scol = 4 * (tx & 7);
    float* obp = out + (((size_t)b * 64 + obch) * HW + y0 + srow) * HW + x0 + scol;
    #pragma unroll
    for (int o = 0; o < 16; o++) {
        *(float4*)(obp + (size_t)o * HWHW) =
            make_float4(acc[o][0].x, acc[o][0].y, acc[o][1].x, acc[o][1].y);
    }
}

// ---------------------------------------------------------------------------
extern "C" void kernel_launch(void* const* d_in, const int* in_sizes, int n_in,
                              void* d_out, int out_size)
{
    const float* x     = (const float*)d_in[0];
    const float* W_in  = (const float*)d_in[1];
    const float* fftf  = (const float*)d_in[2];
    const float* W_dw  = (const float*)d_in[3];
    const float* W_out = (const float*)d_in[4];
    float* out = (float*)d_out;

    const int smem1 = (64 * 256 + HID * 4) * (int)sizeof(float);   // ~67 KB
    const int smem2 = (HID * 64 + 4 * 85 * 9 + 2 * SH_BUF + 2 * SG_BUF) * (int)sizeof(float); // ~104 KB
    cudaFuncSetAttribute(pass1_kernel, cudaFuncAttributeMaxDynamicSharedMemorySize, smem1);
    cudaFuncSetAttribute(pass2_kernel, cudaFuncAttributeMaxDynamicSharedMemorySize, smem2);

    pass1_kernel<<<dim3(2, 128, 4), 256, smem1>>>(x, W_in, fftf);
    pass2_kernel<<<dim3(8, 32, 4), 256, smem2>>>(W_dw, W_out, out);
}

// round 12
// speedup vs baseline: 1.1051x; 1.1051x over previous
#include <cuda_runtime.h>
#include <cuda_bf16.h>

#define DIMC 64
#define HID  170
#define HW   256
#define HWHW (HW * HW)

// sh layout: row stride 38 (conflict-free rows)
#define SH_RS  38
#define SH_CH  380        // 10 * 38
#define SH_GRP 760        // 2 ch * 380
// sG layout: XOR-swizzled rows of 256 words
#define SG_RS  256

// h scratch: [4][170][256][256] f32 = 178 MB (static __device__ => allocation-free)
__device__ float g_h[(size_t)4 * HID * HW * HW];

// Packed dual-FMA (Blackwell f32x2 pipe): d = a*b + c on 2 floats per instr.
__device__ __forceinline__ float2 ffma2(float2 a, float2 b, float2 c) {
    float2 d;
    asm("fma.rn.f32x2 %0, %1, %2, %3;"
        : "=l"(reinterpret_cast<unsigned long long&>(d))
        : "l"(reinterpret_cast<const unsigned long long&>(a)),
          "l"(reinterpret_cast<const unsigned long long&>(b)),
          "l"(reinterpret_cast<const unsigned long long&>(c)));
    return d;
}

__device__ __forceinline__ float f4c(const float4& v, int kk) {
    return (kk == 0) ? v.x : (kk == 1) ? v.y : (kk == 2) ? v.z : v.w;
}

// tanh-approx GELU (matches exact GELU to ~1e-6 rel in our small-|x| regime)
__device__ __forceinline__ float gelu_t(float x) {
    float u = 0.7978845608f * x * (1.f + 0.044715f * x * x);
    float t;
    asm("tanh.approx.f32 %0, %1;" : "=f"(t) : "f"(u));
    return 0.5f * x * (1.f + t);
}

// XOR swizzle on float4 blocks: injective, conflict-free for our access shapes.
__device__ __forceinline__ int sg_addr4(int blk) {
    return 4 * (blk ^ ((blk >> 3) & 7));
}

// ---------------------------------------------------------------------------
// Pass 1: 1x1 conv (64 -> 170) + 2x2 patch spectral filter (4x4 Hadamard map)
// grid (2, 128, 4). block 256. (unchanged — proven ~138us)
// ---------------------------------------------------------------------------
extern "C" __global__ void __launch_bounds__(256, 2)
pass1_kernel(const float* __restrict__ x, const float* __restrict__ W_in,
             const float* __restrict__ fftf)
{
    extern __shared__ float smem[];
    float* sx = smem;               // [64][256] patch-grouped: sx[k*256 + 4*P + s]
    float* sF = sx + 64 * 256;      // [170][4]

    const int tid = threadIdx.x;
    const int b   = blockIdx.z;
    const int py  = blockIdx.y;
    const int c0b = blockIdx.x * 128;

    for (int i = tid; i < HID * 4; i += 256) sF[i] = fftf[i];

    const float* xb = x + (size_t)b * 64 * HWHW;
    for (int idx = tid; idx < 4096; idx += 256) {
        int k  = idx >> 6;
        int r  = (idx >> 5) & 1;
        int c4 = idx & 31;
        float4 v = *(const float4*)(xb + ((size_t)k * HW + 2 * py + r) * HW + c0b + 4 * c4);
        int base = k * 256 + 8 * c4 + 2 * r;
        *(float2*)(sx + base)     = make_float2(v.x, v.y);
        *(float2*)(sx + base + 4) = make_float2(v.z, v.w);
    }
    __syncthreads();

    const int j  = tid & 31;   // patch slots j, j+32
    const int is = tid >> 5;   // channel octet slot (warp id)

    #pragma unroll
    for (int cb = 0; cb < 192; cb += 64) {
        const int cbase = cb + is * 8;
        if (cbase >= HID) continue;

        float2 acc[8][2][2];
        #pragma unroll
        for (int cc = 0; cc < 8; cc++)
            #pragma unroll
            for (int p = 0; p < 2; p++)
                acc[cc][p][0] = acc[cc][p][1] = make_float2(0.f, 0.f);

        const float4* wbase = (const float4*)W_in;
        #pragma unroll
        for (int k4 = 0; k4 < 16; k4++) {
            float4 w[8];
            #pragma unroll
            for (int cc = 0; cc < 8; cc++) {
                int c = cbase + cc;
                w[cc] = __ldg(wbase + (c < HID ? c : 0) * 16 + k4);
            }
            #pragma unroll
            for (int kk = 0; kk < 4; kk++) {
                const float* row = sx + (k4 * 4 + kk) * 256;
                float4 v0 = *(const float4*)(row + 4 * j);
                float4 v1 = *(const float4*)(row + 4 * (j + 32));
                float2 v0lo = make_float2(v0.x, v0.y), v0hi = make_float2(v0.z, v0.w);
                float2 v1lo = make_float2(v1.x, v1.y), v1hi = make_float2(v1.z, v1.w);
                #pragma unroll
                for (int cc = 0; cc < 8; cc++) {
                    float ws = f4c(w[cc], kk);
                    float2 w2 = make_float2(ws, ws);
                    acc[cc][0][0] = ffma2(w2, v0lo, acc[cc][0][0]);
                    acc[cc][0][1] = ffma2(w2, v0hi, acc[cc][0][1]);
                    acc[cc][1][0] = ffma2(w2, v1lo, acc[cc][1][0]);
                    acc[cc][1][1] = ffma2(w2, v1hi, acc[cc][1][1]);
                }
            }
        }

        #pragma unroll
        for (int cc = 0; cc < 8; cc++) {
            int c = cbase + cc;
            if (c >= HID) break;
            float f0 = sF[c * 4 + 0], f1 = sF[c * 4 + 1];
            float f2 = sF[c * 4 + 2], f3 = sF[c * 4 + 3];
            float* hb = g_h + (((size_t)b * HID + c) * HW + 2 * py) * HW + c0b;
            #pragma unroll
            for (int p = 0; p < 2; p++) {
                float a  = acc[cc][p][0].x, bb = acc[cc][p][0].y;
                float cv = acc[cc][p][1].x, dd = acc[cc][p][1].y;
                float X0 = a + bb + cv + dd;
                float X1 = a - bb + cv - dd;
                float X2 = a + bb - cv - dd;
                float X3 = a - bb - cv + dd;
                X0 *= 0.25f * f0; X1 *= 0.25f * f1; X2 *= 0.25f * f2; X3 *= 0.25f * f3;
                float o0 = X0 + X1 + X2 + X3;
                float o1 = X0 - X1 + X2 - X3;
                float o2 = X0 + X1 - X2 - X3;
                float o3 = X0 - X1 - X2 + X3;
                int P = j + 32 * p;
                *(float2*)(hb + 2 * P)      = make_float2(o0, o1);
                *(float2*)(hb + HW + 2 * P) = make_float2(o2, o3);
            }
        }
    }
}

// ---------------------------------------------------------------------------
// Pass 2: depthwise 3x3 + tanh-GELU gate + 1x1 (170->64).
// R8 structure (single-buffered, staging at chunk top, 2 barriers/chunk);
// phase B remapped to 16 outs x 4 px per thread (g-read traffic halved).
// Phase A: groups 0-3: 64 threads x 4 px; group 4: 256 threads x 1 px.
// grid (8, 32, 4): pixel tile 32 wide x 8 tall. block 256.
// ---------------------------------------------------------------------------
extern "C" __global__ void __launch_bounds__(256, 2)
pass2_kernel(const float* __restrict__ W_dw, const float* __restrict__ W_out,
             float* __restrict__ out)
{
    extern __shared__ float smem[];
    float*  sWo  = smem;                          // [170][64] W_out^T
    float2* sDw1 = (float2*)(smem + HID * 64);    // [85][9] (Wdw[2g][t], Wdw[2g+1][t])
    float2* sDw2 = sDw1 + 85 * 9;                 // [85][9] (+170 bank)
    float*  sh   = (float*)(sDw2 + 85 * 9);       // [5 groups][2 ch][10][SH_RS]
    float*  sG   = sh + 5 * SH_GRP;               // [10][SG_RS] swizzled gated chunk

    const int tid = threadIdx.x;
    const int tx = tid & 31, ty = tid >> 5;
    const int b  = blockIdx.z;
    const int x0 = blockIdx.x * 32, y0 = blockIdx.y * 8;

    for (int idx = tid; idx < HID * 64; idx += 256) {
        int c = idx >> 6, o = idx & 63;
        sWo[idx] = W_out[o * HID + c];
    }
    for (int idx = tid; idx < 85 * 9; idx += 256) {
        int g = idx / 9, t = idx - 9 * g;
        sDw1[idx] = make_float2(W_dw[(2 * g) * 9 + t],       W_dw[(2 * g + 1) * 9 + t]);
        sDw2[idx] = make_float2(W_dw[(170 + 2 * g) * 9 + t], W_dw[(171 + 2 * g) * 9 + t]);
    }

    // Staging descriptors: 3 slots/thread covering 680 elements of one group-pair
    const float* gp[3];
    int  soff[3];
    bool sval[3];
    #pragma unroll
    for (int s = 0; s < 3; s++) {
        int idx = tid + 256 * s;
        bool act = idx < 680;
        int ii = act ? idx : 0;
        int ch  = ii >= 340;
        int rem = ii - ch * 340;
        int row = rem / 34, col = rem - row * 34;
        int gy = y0 - 1 + row, gx = x0 - 1 + col;
        bool inb = (gy >= 0) && (gy < HW) && (gx >= 0) && (gx < HW);
        sval[s] = act && inb;
        soff[s] = ch * SH_CH + row * SH_RS + col;
        gp[s] = g_h + (((size_t)b * HID + ch * 85) * HW + (inb ? gy : 0)) * HW + (inb ? gx : 0);
    }

    // phase-A mappings
    const int gi4 = tid >> 6;            // group 0..3 (4px path)
    const int t64 = tid & 63;
    const int ryA = t64 >> 3;            // 0..7
    const int cA  = (t64 & 7) * 4;       // col base 0..28
    const int ryS = tid >> 5;            // group-4 path: 1 px/thread
    const int pxS = tid & 31;
    const int wrA  = sg_addr4(ryA * 8 + (cA >> 2));
    const int wrS4 = sg_addr4((ryS * 32 + pxS) >> 2) + (pxS & 3);

    // phase-B mapping: 16 outs x 4 px per thread
    const int obch = (ty & 3) * 16;      // out base
    const int ph   = ty >> 2;            // px half (0: px<128, 1: px>=128)
    const int rdG  = sg_addr4(ph * 32 + tx);

    float2 acc[16][2];
    #pragma unroll
    for (int o = 0; o < 16; o++) acc[o][0] = acc[o][1] = make_float2(0.f, 0.f);

    __syncthreads();

    for (int ck = 0; ck < 17; ck++) {
        // ---- stage h for 5 groups (batched LDGs, then STS) ----
        {
            float pf[15];
            #pragma unroll
            for (int gi = 0; gi < 5; gi++) {
                size_t goff = (size_t)(ck * 5 + gi) * HWHW;
                #pragma unroll
                for (int s = 0; s < 3; s++)
                    pf[gi * 3 + s] = sval[s] ? __ldg(gp[s] + goff) : 0.f;
            }
            #pragma unroll
            for (int gi = 0; gi < 5; gi++) {
                float* dst = sh + gi * SH_GRP;
                dst[soff[0]] = pf[gi * 3 + 0];
                dst[soff[1]] = pf[gi * 3 + 1];
                if (tid < 680 - 512) dst[soff[2]] = pf[gi * 3 + 2];
            }
        }
        __syncthreads();

        // ---- phase A: dwconv + GELU gate -> sG (swizzled) ----
        // groups 0..3: 64 threads each, 4 px/thread
        {
            int g = ck * 5 + gi4;
            const float*  b0 = sh + gi4 * SH_GRP + ryA * SH_RS + cA;
            const float*  b1 = b0 + SH_CH;
            const float2* w1 = sDw1 + g * 9;
            const float2* w2 = sDw2 + g * 9;
            float2 a1[2][2], a2[2][2];
            #pragma unroll
            for (int u = 0; u < 2; u++)
                #pragma unroll
                for (int v = 0; v < 2; v++) {
                    a1[u][v] = make_float2(0.f, 0.f);
                    a2[u][v] = make_float2(0.f, 0.f);
                }
            #pragma unroll
            for (int r = 0; r < 3; r++) {
                float2 r0 = *(const float2*)(b0 + r * SH_RS);
                float2 r1 = *(const float2*)(b0 + r * SH_RS + 2);
                float2 r2 = *(const float2*)(b0 + r * SH_RS + 4);
                float2 q0 = *(const float2*)(b1 + r * SH_RS);
                float2 q1 = *(const float2*)(b1 + r * SH_RS + 2);
                float2 q2 = *(const float2*)(b1 + r * SH_RS + 4);
                float2 h01[3] = { r0, make_float2(r0.y, r1.x), r1 };
                float2 h23[3] = { r1, make_float2(r1.y, r2.x), r2 };
                float2 p01[3] = { q0, make_float2(q0.y, q1.x), q1 };
                float2 p23[3] = { q1, make_float2(q1.y, q2.x), q2 };
                #pragma unroll
                for (int kx = 0; kx < 3; kx++) {
                    float2 wa = w1[r * 3 + kx];
                    float2 wb = w2[r * 3 + kx];
                    a1[0][0] = ffma2(make_float2(wa.x, wa.x), h01[kx], a1[0][0]);
                    a1[0][1] = ffma2(make_float2(wa.x, wa.x), h23[kx], a1[0][1]);
                    a1[1][0] = ffma2(make_float2(wa.y, wa.y), h01[kx], a1[1][0]);
                    a1[1][1] = ffma2(make_float2(wa.y, wa.y), h23[kx], a1[1][1]);
                    a2[0][0] = ffma2(make_float2(wb.x, wb.x), p01[kx], a2[0][0]);
                    a2[0][1] = ffma2(make_float2(wb.x, wb.x), p23[kx], a2[0][1]);
                    a2[1][0] = ffma2(make_float2(wb.y, wb.y), p01[kx], a2[1][0]);
                    a2[1][1] = ffma2(make_float2(wb.y, wb.y), p23[kx], a2[1][1]);
                }
            }
            #pragma unroll
            for (int chn = 0; chn < 2; chn++) {
                float4 gv;
                gv.x = gelu_t(a1[chn][0].x) * a2[chn][0].x;
                gv.y = gelu_t(a1[chn][0].y) * a2[chn][0].y;
                gv.z = gelu_t(a1[chn][1].x) * a2[chn][1].x;
                gv.w = gelu_t(a1[chn][1].y) * a2[chn][1].y;
                *(float4*)(sG + (2 * gi4 + chn) * SG_RS + wrA) = gv;
            }
        }
        // group 4: all 256 threads, 1 px/thread
        {
            int g = ck * 5 + 4;
            const float*  b0 = sh + 4 * SH_GRP + ryS * SH_RS + pxS;
            const float*  b1 = b0 + SH_CH;
            const float2* w1 = sDw1 + g * 9;
            const float2* w2 = sDw2 + g * 9;
            float2 x1p = make_float2(0.f, 0.f);
            float2 x2p = make_float2(0.f, 0.f);
            #pragma unroll
            for (int ky = 0; ky < 3; ky++) {
                #pragma unroll
                for (int kx = 0; kx < 3; kx++) {
                    float h0 = b0[ky * SH_RS + kx];
                    float h1 = b1[ky * SH_RS + kx];
                    x1p = ffma2(w1[ky * 3 + kx], make_float2(h0, h0), x1p);
                    x2p = ffma2(w2[ky * 3 + kx], make_float2(h1, h1), x2p);
                }
            }
            sG[8 * SG_RS + wrS4] = gelu_t(x1p.x) * x2p.x;
            sG[9 * SG_RS + wrS4] = gelu_t(x1p.y) * x2p.y;
        }
        __syncthreads();

        // ---- phase B: GEMM accumulate (16 outs x 4 px per thread) ----
        #pragma unroll
        for (int kc = 0; kc < 10; kc++) {
            int c = ck * 10 + kc;
            const float4* wv = (const float4*)(sWo + c * 64 + obch);
            float4 w0 = wv[0], w1 = wv[1], w2v = wv[2], w3 = wv[3];
            float4 g = *(const float4*)(sG + kc * SG_RS + rdG);
            float2 glo = make_float2(g.x, g.y);
            float2 ghi = make_float2(g.z, g.w);
            float ws[16] = {w0.x, w0.y, w0.z, w0.w, w1.x, w1.y, w1.z, w1.w,
                            w2v.x, w2v.y, w2v.z, w2v.w, w3.x, w3.y, w3.z, w3.w};
            #pragma unroll
            for (int o = 0; o < 16; o++) {
                float2 wp = make_float2(ws[o], ws[o]);
                acc[o][0] = ffma2(wp, glo, acc[o][0]);
                acc[o][1] = ffma2(wp, ghi, acc[o][1]);
            }
        }
        // phase B reads only sG/sWo; next-iter sh writes are fenced by the
        // barrier at the top of the next iteration before phase A reads them.
    }

    // ---- store: thread owns outs [obch, obch+16) at 4 px ----
    const int srow = ph * 4 + (tx >> 3);
    const int scol = 4 * (tx & 7);
    float* obp = out + (((size_t)b * 64 + obch) * HW + y0 + srow) * HW + x0 + scol;
    #pragma unroll
    for (int o = 0; o < 16; o++) {
        *(float4*)(obp + (size_t)o * HWHW) =
            make_float4(acc[o][0].x, acc[o][0].y, acc[o][1].x, acc[o][1].y);
    }
}

// ---------------------------------------------------------------------------
extern "C" void kernel_launch(void* const* d_in, const int* in_sizes, int n_in,
                              void* d_out, int out_size)
{
    const float* x     = (const float*)d_in[0];
    const float* W_in  = (const float*)d_in[1];
    const float* fftf  = (const float*)d_in[2];
    const float* W_dw  = (const float*)d_in[3];
    const float* W_out = (const float*)d_in[4];
    float* out = (float*)d_out;

    const int smem1 = (64 * 256 + HID * 4) * (int)sizeof(float);   // ~67 KB
    const int smem2 = (HID * 64 + 4 * 85 * 9 + 5 * SH_GRP + 10 * SG_RS) * (int)sizeof(float); // ~80 KB
    cudaFuncSetAttribute(pass1_kernel, cudaFuncAttributeMaxDynamicSharedMemorySize, smem1);
    cudaFuncSetAttribute(pass2_kernel, cudaFuncAttributeMaxDynamicSharedMemorySize, smem2);

    pass1_kernel<<<dim3(2, 128, 4), 256, smem1>>>(x, W_in, fftf);
    pass2_kernel<<<dim3(8, 32, 4), 256, smem2>>>(W_dw, W_out, out);
}

// round 16
// speedup vs baseline: 1.1298x; 1.0223x over previous
#include <cuda_runtime.h>
#include <cuda_bf16.h>
#include <cstdint>

#define DIMC 64
#define HID  170
#define HW   256
#define HWHW (HW * HW)

// sh layout: row stride 38 (conflict-free rows)
#define SH_RS  38
#define SH_CH  380        // 10 * 38
#define SH_GRP 760        // 2 ch * 380
// sG layout: XOR-swizzled rows of 256 words
#define SG_RS  256

// h scratch: [4][170][256][256] f32 = 178 MB (static __device__ => allocation-free)
__device__ float g_h[(size_t)4 * HID * HW * HW];

// Packed dual-FMA (Blackwell f32x2 pipe): d = a*b + c on 2 floats per instr.
__device__ __forceinline__ float2 ffma2(float2 a, float2 b, float2 c) {
    float2 d;
    asm("fma.rn.f32x2 %0, %1, %2, %3;"
        : "=l"(reinterpret_cast<unsigned long long&>(d))
        : "l"(reinterpret_cast<const unsigned long long&>(a)),
          "l"(reinterpret_cast<const unsigned long long&>(b)),
          "l"(reinterpret_cast<const unsigned long long&>(c)));
    return d;
}

__device__ __forceinline__ float f4c(const float4& v, int kk) {
    return (kk == 0) ? v.x : (kk == 1) ? v.y : (kk == 2) ? v.z : v.w;
}

// tanh-approx GELU (matches exact GELU to ~1e-6 rel in our small-|x| regime)
__device__ __forceinline__ float gelu_t(float x) {
    float u = 0.7978845608f * x * (1.f + 0.044715f * x * x);
    float t;
    asm("tanh.approx.f32 %0, %1;" : "=f"(t) : "f"(u));
    return 0.5f * x * (1.f + t);
}

// XOR swizzle on float4 blocks: injective, conflict-free for our access shapes.
__device__ __forceinline__ int sg_addr4(int blk) {
    return 4 * (blk ^ ((blk >> 3) & 7));
}

// ---------------------------------------------------------------------------
// Pass 1: 1x1 conv (64 -> 170) + 2x2 patch spectral filter (4x4 Hadamard map)
// grid (2, 128, 4). block 256. (unchanged — proven ~138us)
// ---------------------------------------------------------------------------
extern "C" __global__ void __launch_bounds__(256, 2)
pass1_kernel(const float* __restrict__ x, const float* __restrict__ W_in,
             const float* __restrict__ fftf)
{
    extern __shared__ float smem[];
    float* sx = smem;               // [64][256] patch-grouped: sx[k*256 + 4*P + s]
    float* sF = sx + 64 * 256;      // [170][4]

    const int tid = threadIdx.x;
    const int b   = blockIdx.z;
    const int py  = blockIdx.y;
    const int c0b = blockIdx.x * 128;

    for (int i = tid; i < HID * 4; i += 256) sF[i] = fftf[i];

    const float* xb = x + (size_t)b * 64 * HWHW;
    for (int idx = tid; idx < 4096; idx += 256) {
        int k  = idx >> 6;
        int r  = (idx >> 5) & 1;
        int c4 = idx & 31;
        float4 v = *(const float4*)(xb + ((size_t)k * HW + 2 * py + r) * HW + c0b + 4 * c4);
        int base = k * 256 + 8 * c4 + 2 * r;
        *(float2*)(sx + base)     = make_float2(v.x, v.y);
        *(float2*)(sx + base + 4) = make_float2(v.z, v.w);
    }
    __syncthreads();

    const int j  = tid & 31;   // patch slots j, j+32
    const int is = tid >> 5;   // channel octet slot (warp id)

    #pragma unroll
    for (int cb = 0; cb < 192; cb += 64) {
        const int cbase = cb + is * 8;
        if (cbase >= HID) continue;

        float2 acc[8][2][2];
        #pragma unroll
        for (int cc = 0; cc < 8; cc++)
            #pragma unroll
            for (int p = 0; p < 2; p++)
                acc[cc][p][0] = acc[cc][p][1] = make_float2(0.f, 0.f);

        const float4* wbase = (const float4*)W_in;
        #pragma unroll
        for (int k4 = 0; k4 < 16; k4++) {
            float4 w[8];
            #pragma unroll
            for (int cc = 0; cc < 8; cc++) {
                int c = cbase + cc;
                w[cc] = __ldg(wbase + (c < HID ? c : 0) * 16 + k4);
            }
            #pragma unroll
            for (int kk = 0; kk < 4; kk++) {
                const float* row = sx + (k4 * 4 + kk) * 256;
                float4 v0 = *(const float4*)(row + 4 * j);
                float4 v1 = *(const float4*)(row + 4 * (j + 32));
                float2 v0lo = make_float2(v0.x, v0.y), v0hi = make_float2(v0.z, v0.w);
                float2 v1lo = make_float2(v1.x, v1.y), v1hi = make_float2(v1.z, v1.w);
                #pragma unroll
                for (int cc = 0; cc < 8; cc++) {
                    float ws = f4c(w[cc], kk);
                    float2 w2 = make_float2(ws, ws);
                    acc[cc][0][0] = ffma2(w2, v0lo, acc[cc][0][0]);
                    acc[cc][0][1] = ffma2(w2, v0hi, acc[cc][0][1]);
                    acc[cc][1][0] = ffma2(w2, v1lo, acc[cc][1][0]);
                    acc[cc][1][1] = ffma2(w2, v1hi, acc[cc][1][1]);
                }
            }
        }

        #pragma unroll
        for (int cc = 0; cc < 8; cc++) {
            int c = cbase + cc;
            if (c >= HID) break;
            float f0 = sF[c * 4 + 0], f1 = sF[c * 4 + 1];
            float f2 = sF[c * 4 + 2], f3 = sF[c * 4 + 3];
            float* hb = g_h + (((size_t)b * HID + c) * HW + 2 * py) * HW + c0b;
            #pragma unroll
            for (int p = 0; p < 2; p++) {
                float a  = acc[cc][p][0].x, bb = acc[cc][p][0].y;
                float cv = acc[cc][p][1].x, dd = acc[cc][p][1].y;
                float X0 = a + bb + cv + dd;
                float X1 = a - bb + cv - dd;
                float X2 = a + bb - cv - dd;
                float X3 = a - bb - cv + dd;
                X0 *= 0.25f * f0; X1 *= 0.25f * f1; X2 *= 0.25f * f2; X3 *= 0.25f * f3;
                float o0 = X0 + X1 + X2 + X3;
                float o1 = X0 - X1 + X2 - X3;
                float o2 = X0 + X1 - X2 - X3;
                float o3 = X0 - X1 - X2 + X3;
                int P = j + 32 * p;
                *(float2*)(hb + 2 * P)      = make_float2(o0, o1);
                *(float2*)(hb + HW + 2 * P) = make_float2(o2, o3);
            }
        }
    }
}

// ---------------------------------------------------------------------------
// Pass 2: depthwise 3x3 + tanh-GELU gate + 1x1 (170->64).
// R8 proven structure (single-buffered, staging at chunk top, 2 barriers).
// Phase A: ALL 5 groups via the 4-px/thread path using 320 slots over 256
//          threads (threads 0-63 take a second slot for group 4) — 17% less
//          phase-A crossbar than the old 1-px group-4 path.
// Phase B: 8 outs x 8 px per thread (best measured mapping).
// grid (8, 32, 4): pixel tile 32 wide x 8 tall. block 256.
// ---------------------------------------------------------------------------
extern "C" __global__ void __launch_bounds__(256, 2)
pass2_kernel(const float* __restrict__ W_dw, const float* __restrict__ W_out,
             float* __restrict__ out)
{
    extern __shared__ float smem[];
    float*  sWo  = smem;                          // [170][64] W_out^T
    float2* sDw1 = (float2*)(smem + HID * 64);    // [85][9] (Wdw[2g][t], Wdw[2g+1][t])
    float2* sDw2 = sDw1 + 85 * 9;                 // [85][9] (+170 bank)
    float*  sh   = (float*)(sDw2 + 85 * 9);       // [5 groups][2 ch][10][SH_RS]
    float*  sG   = sh + 5 * SH_GRP;               // [10][SG_RS] swizzled gated chunk

    const int tid = threadIdx.x;
    const int tx = tid & 31, ty = tid >> 5;
    const int b  = blockIdx.z;
    const int x0 = blockIdx.x * 32, y0 = blockIdx.y * 8;
    const int mi = ty;        // out block: outs mi*8 .. mi*8+7
    const int nj = tx;        // px  block: px  nj*8 .. nj*8+7

    for (int idx = tid; idx < HID * 64; idx += 256) {
        int c = idx >> 6, o = idx & 63;
        sWo[idx] = W_out[o * HID + c];
    }
    for (int idx = tid; idx < 85 * 9; idx += 256) {
        int g = idx / 9, t = idx - 9 * g;
        sDw1[idx] = make_float2(W_dw[(2 * g) * 9 + t],       W_dw[(2 * g + 1) * 9 + t]);
        sDw2[idx] = make_float2(W_dw[(170 + 2 * g) * 9 + t], W_dw[(171 + 2 * g) * 9 + t]);
    }

    // Staging descriptors: 3 slots/thread covering 680 elements of one group-pair
    const float* gp[3];
    int  soff[3];
    bool sval[3];
    #pragma unroll
    for (int s = 0; s < 3; s++) {
        int idx = tid + 256 * s;
        bool act = idx < 680;
        int ii = act ? idx : 0;
        int ch  = ii >= 340;
        int rem = ii - ch * 340;
        int row = rem / 34, col = rem - row * 34;
        int gy = y0 - 1 + row, gx = x0 - 1 + col;
        bool inb = (gy >= 0) && (gy < HW) && (gx >= 0) && (gx < HW);
        sval[s] = act && inb;
        soff[s] = ch * SH_CH + row * SH_RS + col;
        gp[s] = g_h + (((size_t)b * HID + ch * 85) * HW + (inb ? gy : 0)) * HW + (inb ? gx : 0);
    }

    // phase-A slot mappings: slot = tid (groups 0..3) and slot = 256+tid (group 4, tid<64)
    const int gi4 = tid >> 6;            // first-slot group 0..3
    const int t64 = tid & 63;
    const int ryA = t64 >> 3;            // 0..7
    const int cA  = (t64 & 7) * 4;       // col base 0..28
    const int wrA = sg_addr4(ryA * 8 + (cA >> 2));
    const int ryB = (tid & 63) >> 3;     // second-slot (group 4) row — valid tid<64
    const int cB  = (tid & 7) * 4;
    const int wrB = sg_addr4((tid >> 3) * 8 + (tid & 7));   // = sg_addr4(ryB*8 + cB/4) for tid<64

    // phase-B read offsets (8 outs x 8 px)
    const int sB  = (nj >> 2) & 7;
    const int rdA = 4 * ((2 * nj) ^ sB);
    const int rdB = 4 * ((2 * nj + 1) ^ sB);

    float2 acc[8][4];
    #pragma unroll
    for (int o = 0; o < 8; o++)
        #pragma unroll
        for (int pp = 0; pp < 4; pp++) acc[o][pp] = make_float2(0.f, 0.f);

    __syncthreads();

    for (int ck = 0; ck < 17; ck++) {
        // ---- stage h for 5 groups (batched LDGs, then STS) ----
        {
            float pf[15];
            #pragma unroll
            for (int gi = 0; gi < 5; gi++) {
                size_t goff = (size_t)(ck * 5 + gi) * HWHW;
                #pragma unroll
                for (int s = 0; s < 3; s++)
                    pf[gi * 3 + s] = sval[s] ? __ldg(gp[s] + goff) : 0.f;
            }
            #pragma unroll
            for (int gi = 0; gi < 5; gi++) {
                float* dst = sh + gi * SH_GRP;
                dst[soff[0]] = pf[gi * 3 + 0];
                dst[soff[1]] = pf[gi * 3 + 1];
                if (tid < 680 - 512) dst[soff[2]] = pf[gi * 3 + 2];
            }
        }
        __syncthreads();

        // ---- phase A: dwconv + GELU gate -> sG, 4-px path for ALL 5 groups ----
        #pragma unroll
        for (int sw = 0; sw < 2; sw++) {
            const bool active = (sw == 0) || (tid < 64);
            if (active) {
                const int gi = (sw == 0) ? gi4 : 4;
                const int ry = (sw == 0) ? ryA : ryB;
                const int ca = (sw == 0) ? cA  : cB;
                const int wr = (sw == 0) ? wrA : wrB;
                const int g  = ck * 5 + gi;
                const float*  b0 = sh + gi * SH_GRP + ry * SH_RS + ca;
                const float*  b1 = b0 + SH_CH;
                const float2* w1 = sDw1 + g * 9;
                const float2* w2 = sDw2 + g * 9;
                float2 a1[2][2], a2[2][2];
                #pragma unroll
                for (int u = 0; u < 2; u++)
                    #pragma unroll
                    for (int v = 0; v < 2; v++) {
                        a1[u][v] = make_float2(0.f, 0.f);
                        a2[u][v] = make_float2(0.f, 0.f);
                    }
                #pragma unroll
                for (int r = 0; r < 3; r++) {
                    float2 r0 = *(const float2*)(b0 + r * SH_RS);
                    float2 r1 = *(const float2*)(b0 + r * SH_RS + 2);
                    float2 r2 = *(const float2*)(b0 + r * SH_RS + 4);
                    float2 q0 = *(const float2*)(b1 + r * SH_RS);
                    float2 q1 = *(const float2*)(b1 + r * SH_RS + 2);
                    float2 q2 = *(const float2*)(b1 + r * SH_RS + 4);
                    float2 h01[3] = { r0, make_float2(r0.y, r1.x), r1 };
                    float2 h23[3] = { r1, make_float2(r1.y, r2.x), r2 };
                    float2 p01[3] = { q0, make_float2(q0.y, q1.x), q1 };
                    float2 p23[3] = { q1, make_float2(q1.y, q2.x), q2 };
                    #pragma unroll
                    for (int kx = 0; kx < 3; kx++) {
                        float2 wa = w1[r * 3 + kx];
                        float2 wb = w2[r * 3 + kx];
                        a1[0][0] = ffma2(make_float2(wa.x, wa.x), h01[kx], a1[0][0]);
                        a1[0][1] = ffma2(make_float2(wa.x, wa.x), h23[kx], a1[0][1]);
                        a1[1][0] = ffma2(make_float2(wa.y, wa.y), h01[kx], a1[1][0]);
                        a1[1][1] = ffma2(make_float2(wa.y, wa.y), h23[kx], a1[1][1]);
                        a2[0][0] = ffma2(make_float2(wb.x, wb.x), p01[kx], a2[0][0]);
                        a2[0][1] = ffma2(make_float2(wb.x, wb.x), p23[kx], a2[0][1]);
                        a2[1][0] = ffma2(make_float2(wb.y, wb.y), p01[kx], a2[1][0]);
                        a2[1][1] = ffma2(make_float2(wb.y, wb.y), p23[kx], a2[1][1]);
                    }
                }
                #pragma unroll
                for (int chn = 0; chn < 2; chn++) {
                    float4 gv;
                    gv.x = gelu_t(a1[chn][0].x) * a2[chn][0].x;
                    gv.y = gelu_t(a1[chn][0].y) * a2[chn][0].y;
                    gv.z = gelu_t(a1[chn][1].x) * a2[chn][1].x;
                    gv.w = gelu_t(a1[chn][1].y) * a2[chn][1].y;
                    *(float4*)(sG + (2 * gi + chn) * SG_RS + wr) = gv;
                }
            }
        }
        __syncthreads();

        // ---- phase B: GEMM accumulate (8 outs x 8 px per thread) ----
        #pragma unroll
        for (int kc = 0; kc < 10; kc++) {
            int c = ck * 10 + kc;
            const float4* wv = (const float4*)(sWo + c * 64 + mi * 8);
            float4 wA = wv[0], wB = wv[1];
            float4 gA = *(const float4*)(sG + kc * SG_RS + rdA);
            float4 gB = *(const float4*)(sG + kc * SG_RS + rdB);
            float2 g0 = make_float2(gA.x, gA.y);
            float2 g1 = make_float2(gA.z, gA.w);
            float2 g2 = make_float2(gB.x, gB.y);
            float2 g3 = make_float2(gB.z, gB.w);
            float ws[8] = {wA.x, wA.y, wA.z, wA.w, wB.x, wB.y, wB.z, wB.w};
            #pragma unroll
            for (int o = 0; o < 8; o++) {
                float2 w2 = make_float2(ws[o], ws[o]);
                acc[o][0] = ffma2(w2, g0, acc[o][0]);
                acc[o][1] = ffma2(w2, g1, acc[o][1]);
                acc[o][2] = ffma2(w2, g2, acc[o][2]);
                acc[o][3] = ffma2(w2, g3, acc[o][3]);
            }
        }
        // phase B reads only sG/sWo; next-iter sh writes are fenced by the
        // barrier at the top of the next iteration before phase A reads them.
    }

    // ---- store: thread's 8 px = one row segment of 8 cols ----
    const int orow = nj >> 2;
    const int ocol = (nj & 3) * 8;
    float* ob = out + (((size_t)b * 64 + mi * 8) * HW + y0 + orow) * HW + x0 + ocol;
    #pragma unroll
    for (int o = 0; o < 8; o++) {
        float4 v0 = make_float4(acc[o][0].x, acc[o][0].y, acc[o][1].x, acc[o][1].y);
        float4 v1 = make_float4(acc[o][2].x, acc[o][2].y, acc[o][3].x, acc[o][3].y);
        *(float4*)(ob + (size_t)o * HWHW)     = v0;
        *(float4*)(ob + (size_t)o * HWHW + 4) = v1;
    }
}

// ---------------------------------------------------------------------------
extern "C" void kernel_launch(void* const* d_in, const int* in_sizes, int n_in,
                              void* d_out, int out_size)
{
    const float* x     = (const float*)d_in[0];
    const float* W_in  = (const float*)d_in[1];
    const float* fftf  = (const float*)d_in[2];
    const float* W_dw  = (const float*)d_in[3];
    const float* W_out = (const float*)d_in[4];
    float* out = (float*)d_out;

    const int smem1 = (64 * 256 + HID * 4) * (int)sizeof(float);   // ~67 KB
    const int smem2 = (HID * 64 + 4 * 85 * 9 + 5 * SH_GRP + 10 * SG_RS) * (int)sizeof(float); // ~80 KB
    cudaFuncSetAttribute(pass1_kernel, cudaFuncAttributeMaxDynamicSharedMemorySize, smem1);
    cudaFuncSetAttribute(pass2_kernel, cudaFuncAttributeMaxDynamicSharedMemorySize, smem2);

    pass1_kernel<<<dim3(2, 128, 4), 256, smem1>>>(x, W_in, fftf);
    pass2_kernel<<<dim3(8, 32, 4), 256, smem2>>>(W_dw, W_out, out);
}

// round 17
// speedup vs baseline: 1.1571x; 1.0242x over previous
#include <cuda_runtime.h>
#include <cuda_bf16.h>
#include <cuda_fp16.h>
#include <cstdint>

#define DIMC 64
#define HID  170
#define HW   256
#define HWHW (HW * HW)

// sh layout: row stride 38 (conflict-free rows)
#define SH_RS  38
#define SH_CH  380        // 10 * 38
#define SH_GRP 760        // 2 ch * 380
// sG layout: XOR-swizzled rows of 256 words
#define SG_RS  256

// h scratch: [4][170][256][256] fp16 = 89 MB (static __device__ => allocation-free)
__device__ __half g_h[(size_t)4 * HID * HW * HW];

// Packed dual-FMA (Blackwell f32x2 pipe): d = a*b + c on 2 floats per instr.
__device__ __forceinline__ float2 ffma2(float2 a, float2 b, float2 c) {
    float2 d;
    asm("fma.rn.f32x2 %0, %1, %2, %3;"
        : "=l"(reinterpret_cast<unsigned long long&>(d))
        : "l"(reinterpret_cast<const unsigned long long&>(a)),
          "l"(reinterpret_cast<const unsigned long long&>(b)),
          "l"(reinterpret_cast<const unsigned long long&>(c)));
    return d;
}

__device__ __forceinline__ float f4c(const float4& v, int kk) {
    return (kk == 0) ? v.x : (kk == 1) ? v.y : (kk == 2) ? v.z : v.w;
}

// tanh-approx GELU (matches exact GELU to ~1e-6 rel in our small-|x| regime)
__device__ __forceinline__ float gelu_t(float x) {
    float u = 0.7978845608f * x * (1.f + 0.044715f * x * x);
    float t;
    asm("tanh.approx.f32 %0, %1;" : "=f"(t) : "f"(u));
    return 0.5f * x * (1.f + t);
}

// XOR swizzle on float4 blocks: injective, conflict-free for our access shapes.
__device__ __forceinline__ int sg_addr4(int blk) {
    return 4 * (blk ^ ((blk >> 3) & 7));
}

// ---------------------------------------------------------------------------
// Pass 1: 1x1 conv (64 -> 170) + 2x2 patch spectral filter (4x4 Hadamard map)
// grid (2, 128, 4). block 256. h written as fp16 (HBM bytes halved).
// ---------------------------------------------------------------------------
extern "C" __global__ void __launch_bounds__(256, 2)
pass1_kernel(const float* __restrict__ x, const float* __restrict__ W_in,
             const float* __restrict__ fftf)
{
    extern __shared__ float smem[];
    float* sx = smem;               // [64][256] patch-grouped: sx[k*256 + 4*P + s]
    float* sF = sx + 64 * 256;      // [170][4]

    const int tid = threadIdx.x;
    const int b   = blockIdx.z;
    const int py  = blockIdx.y;
    const int c0b = blockIdx.x * 128;

    for (int i = tid; i < HID * 4; i += 256) sF[i] = fftf[i];

    const float* xb = x + (size_t)b * 64 * HWHW;
    for (int idx = tid; idx < 4096; idx += 256) {
        int k  = idx >> 6;
        int r  = (idx >> 5) & 1;
        int c4 = idx & 31;
        float4 v = *(const float4*)(xb + ((size_t)k * HW + 2 * py + r) * HW + c0b + 4 * c4);
        int base = k * 256 + 8 * c4 + 2 * r;
        *(float2*)(sx + base)     = make_float2(v.x, v.y);
        *(float2*)(sx + base + 4) = make_float2(v.z, v.w);
    }
    __syncthreads();

    const int j  = tid & 31;   // patch slots j, j+32
    const int is = tid >> 5;   // channel octet slot (warp id)

    #pragma unroll
    for (int cb = 0; cb < 192; cb += 64) {
        const int cbase = cb + is * 8;
        if (cbase >= HID) continue;

        float2 acc[8][2][2];
        #pragma unroll
        for (int cc = 0; cc < 8; cc++)
            #pragma unroll
            for (int p = 0; p < 2; p++)
                acc[cc][p][0] = acc[cc][p][1] = make_float2(0.f, 0.f);

        const float4* wbase = (const float4*)W_in;
        #pragma unroll
        for (int k4 = 0; k4 < 16; k4++) {
            float4 w[8];
            #pragma unroll
            for (int cc = 0; cc < 8; cc++) {
                int c = cbase + cc;
                w[cc] = __ldg(wbase + (c < HID ? c : 0) * 16 + k4);
            }
            #pragma unroll
            for (int kk = 0; kk < 4; kk++) {
                const float* row = sx + (k4 * 4 + kk) * 256;
                float4 v0 = *(const float4*)(row + 4 * j);
                float4 v1 = *(const float4*)(row + 4 * (j + 32));
                float2 v0lo = make_float2(v0.x, v0.y), v0hi = make_float2(v0.z, v0.w);
                float2 v1lo = make_float2(v1.x, v1.y), v1hi = make_float2(v1.z, v1.w);
                #pragma unroll
                for (int cc = 0; cc < 8; cc++) {
                    float ws = f4c(w[cc], kk);
                    float2 w2 = make_float2(ws, ws);
                    acc[cc][0][0] = ffma2(w2, v0lo, acc[cc][0][0]);
                    acc[cc][0][1] = ffma2(w2, v0hi, acc[cc][0][1]);
                    acc[cc][1][0] = ffma2(w2, v1lo, acc[cc][1][0]);
                    acc[cc][1][1] = ffma2(w2, v1hi, acc[cc][1][1]);
                }
            }
        }

        #pragma unroll
        for (int cc = 0; cc < 8; cc++) {
            int c = cbase + cc;
            if (c >= HID) break;
            float f0 = sF[c * 4 + 0], f1 = sF[c * 4 + 1];
            float f2 = sF[c * 4 + 2], f3 = sF[c * 4 + 3];
            __half* hb = g_h + (((size_t)b * HID + c) * HW + 2 * py) * HW + c0b;
            #pragma unroll
            for (int p = 0; p < 2; p++) {
                float a  = acc[cc][p][0].x, bb = acc[cc][p][0].y;
                float cv = acc[cc][p][1].x, dd = acc[cc][p][1].y;
                float X0 = a + bb + cv + dd;
                float X1 = a - bb + cv - dd;
                float X2 = a + bb - cv - dd;
                float X3 = a - bb - cv + dd;
                X0 *= 0.25f * f0; X1 *= 0.25f * f1; X2 *= 0.25f * f2; X3 *= 0.25f * f3;
                float o0 = X0 + X1 + X2 + X3;
                float o1 = X0 - X1 + X2 - X3;
                float o2 = X0 + X1 - X2 - X3;
                float o3 = X0 - X1 - X2 + X3;
                int P = j + 32 * p;
                *(half2*)(hb + 2 * P)      = __floats2half2_rn(o0, o1);
                *(half2*)(hb + HW + 2 * P) = __floats2half2_rn(o2, o3);
            }
        }
    }
}

// ---------------------------------------------------------------------------
// Pass 2: depthwise 3x3 + tanh-GELU gate + 1x1 (170->64).
// R16 proven structure; g_h read as fp16 (HBM bytes halved), converted to f32
// at STS time — all compute stays f32.
// Phase A: ALL 5 groups via the 4-px/thread path (320 slots over 256 threads).
// Phase B: 8 outs x 8 px per thread.
// grid (8, 32, 4): pixel tile 32 wide x 8 tall. block 256.
// ---------------------------------------------------------------------------
extern "C" __global__ void __launch_bounds__(256, 2)
pass2_kernel(const float* __restrict__ W_dw, const float* __restrict__ W_out,
             float* __restrict__ out)
{
    extern __shared__ float smem[];
    float*  sWo  = smem;                          // [170][64] W_out^T
    float2* sDw1 = (float2*)(smem + HID * 64);    // [85][9] (Wdw[2g][t], Wdw[2g+1][t])
    float2* sDw2 = sDw1 + 85 * 9;                 // [85][9] (+170 bank)
    float*  sh   = (float*)(sDw2 + 85 * 9);       // [5 groups][2 ch][10][SH_RS]
    float*  sG   = sh + 5 * SH_GRP;               // [10][SG_RS] swizzled gated chunk

    const int tid = threadIdx.x;
    const int tx = tid & 31, ty = tid >> 5;
    const int b  = blockIdx.z;
    const int x0 = blockIdx.x * 32, y0 = blockIdx.y * 8;
    const int mi = ty;        // out block: outs mi*8 .. mi*8+7
    const int nj = tx;        // px  block: px  nj*8 .. nj*8+7

    for (int idx = tid; idx < HID * 64; idx += 256) {
        int c = idx >> 6, o = idx & 63;
        sWo[idx] = W_out[o * HID + c];
    }
    for (int idx = tid; idx < 85 * 9; idx += 256) {
        int g = idx / 9, t = idx - 9 * g;
        sDw1[idx] = make_float2(W_dw[(2 * g) * 9 + t],       W_dw[(2 * g + 1) * 9 + t]);
        sDw2[idx] = make_float2(W_dw[(170 + 2 * g) * 9 + t], W_dw[(171 + 2 * g) * 9 + t]);
    }

    // Staging descriptors: 3 slots/thread covering 680 elements of one group-pair
    const __half* gp[3];
    int  soff[3];
    bool sval[3];
    #pragma unroll
    for (int s = 0; s < 3; s++) {
        int idx = tid + 256 * s;
        bool act = idx < 680;
        int ii = act ? idx : 0;
        int ch  = ii >= 340;
        int rem = ii - ch * 340;
        int row = rem / 34, col = rem - row * 34;
        int gy = y0 - 1 + row, gx = x0 - 1 + col;
        bool inb = (gy >= 0) && (gy < HW) && (gx >= 0) && (gx < HW);
        sval[s] = act && inb;
        soff[s] = ch * SH_CH + row * SH_RS + col;
        gp[s] = g_h + (((size_t)b * HID + ch * 85) * HW + (inb ? gy : 0)) * HW + (inb ? gx : 0);
    }

    // phase-A slot mappings: slot = tid (groups 0..3) and slot = 256+tid (group 4, tid<64)
    const int gi4 = tid >> 6;            // first-slot group 0..3
    const int t64 = tid & 63;
    const int ryA = t64 >> 3;            // 0..7
    const int cA  = (t64 & 7) * 4;       // col base 0..28
    const int wrA = sg_addr4(ryA * 8 + (cA >> 2));
    const int ryB = (tid & 63) >> 3;     // second-slot (group 4) row — valid tid<64
    const int cB  = (tid & 7) * 4;
    const int wrB = sg_addr4((tid >> 3) * 8 + (tid & 7));   // valid for tid<64

    // phase-B read offsets (8 outs x 8 px)
    const int sB  = (nj >> 2) & 7;
    const int rdA = 4 * ((2 * nj) ^ sB);
    const int rdB = 4 * ((2 * nj + 1) ^ sB);

    float2 acc[8][4];
    #pragma unroll
    for (int o = 0; o < 8; o++)
        #pragma unroll
        for (int pp = 0; pp < 4; pp++) acc[o][pp] = make_float2(0.f, 0.f);

    __syncthreads();

    for (int ck = 0; ck < 17; ck++) {
        // ---- stage h for 5 groups (batched fp16 LDGs -> f32 STS) ----
        {
            float pf[15];
            #pragma unroll
            for (int gi = 0; gi < 5; gi++) {
                size_t goff = (size_t)(ck * 5 + gi) * HWHW;
                #pragma unroll
                for (int s = 0; s < 3; s++)
                    pf[gi * 3 + s] = sval[s] ? __half2float(__ldg(gp[s] + goff)) : 0.f;
            }
            #pragma unroll
            for (int gi = 0; gi < 5; gi++) {
                float* dst = sh + gi * SH_GRP;
                dst[soff[0]] = pf[gi * 3 + 0];
                dst[soff[1]] = pf[gi * 3 + 1];
                if (tid < 680 - 512) dst[soff[2]] = pf[gi * 3 + 2];
            }
        }
        __syncthreads();

        // ---- phase A: dwconv + GELU gate -> sG, 4-px path for ALL 5 groups ----
        #pragma unroll
        for (int sw = 0; sw < 2; sw++) {
            const bool active = (sw == 0) || (tid < 64);
            if (active) {
                const int gi = (sw == 0) ? gi4 : 4;
                const int ry = (sw == 0) ? ryA : ryB;
                const int ca = (sw == 0) ? cA  : cB;
                const int wr = (sw == 0) ? wrA : wrB;
                const int g  = ck * 5 + gi;
                const float*  b0 = sh + gi * SH_GRP + ry * SH_RS + ca;
                const float*  b1 = b0 + SH_CH;
                const float2* w1 = sDw1 + g * 9;
                const float2* w2 = sDw2 + g * 9;
                float2 a1[2][2], a2[2][2];
                #pragma unroll
                for (int u = 0; u < 2; u++)
                    #pragma unroll
                    for (int v = 0; v < 2; v++) {
                        a1[u][v] = make_float2(0.f, 0.f);
                        a2[u][v] = make_float2(0.f, 0.f);
                    }
                #pragma unroll
                for (int r = 0; r < 3; r++) {
                    float2 r0 = *(const float2*)(b0 + r * SH_RS);
                    float2 r1 = *(const float2*)(b0 + r * SH_RS + 2);
                    float2 r2 = *(const float2*)(b0 + r * SH_RS + 4);
                    float2 q0 = *(const float2*)(b1 + r * SH_RS);
                    float2 q1 = *(const float2*)(b1 + r * SH_RS + 2);
                    float2 q2 = *(const float2*)(b1 + r * SH_RS + 4);
                    float2 h01[3] = { r0, make_float2(r0.y, r1.x), r1 };
                    float2 h23[3] = { r1, make_float2(r1.y, r2.x), r2 };
                    float2 p01[3] = { q0, make_float2(q0.y, q1.x), q1 };
                    float2 p23[3] = { q1, make_float2(q1.y, q2.x), q2 };
                    #pragma unroll
                    for (int kx = 0; kx < 3; kx++) {
                        float2 wa = w1[r * 3 + kx];
                        float2 wb = w2[r * 3 + kx];
                        a1[0][0] = ffma2(make_float2(wa.x, wa.x), h01[kx], a1[0][0]);
                        a1[0][1] = ffma2(make_float2(wa.x, wa.x), h23[kx], a1[0][1]);
                        a1[1][0] = ffma2(make_float2(wa.y, wa.y), h01[kx], a1[1][0]);
                        a1[1][1] = ffma2(make_float2(wa.y, wa.y), h23[kx], a1[1][1]);
                        a2[0][0] = ffma2(make_float2(wb.x, wb.x), p01[kx], a2[0][0]);
                        a2[0][1] = ffma2(make_float2(wb.x, wb.x), p23[kx], a2[0][1]);
                        a2[1][0] = ffma2(make_float2(wb.y, wb.y), p01[kx], a2[1][0]);
                        a2[1][1] = ffma2(make_float2(wb.y, wb.y), p23[kx], a2[1][1]);
                    }
                }
                #pragma unroll
                for (int chn = 0; chn < 2; chn++) {
                    float4 gv;
                    gv.x = gelu_t(a1[chn][0].x) * a2[chn][0].x;
                    gv.y = gelu_t(a1[chn][0].y) * a2[chn][0].y;
                    gv.z = gelu_t(a1[chn][1].x) * a2[chn][1].x;
                    gv.w = gelu_t(a1[chn][1].y) * a2[chn][1].y;
                    *(float4*)(sG + (2 * gi + chn) * SG_RS + wr) = gv;
                }
            }
        }
        __syncthreads();

        // ---- phase B: GEMM accumulate (8 outs x 8 px per thread) ----
        #pragma unroll
        for (int kc = 0; kc < 10; kc++) {
            int c = ck * 10 + kc;
            const float4* wv = (const float4*)(sWo + c * 64 + mi * 8);
            float4 wA = wv[0], wB = wv[1];
            float4 gA = *(const float4*)(sG + kc * SG_RS + rdA);
            float4 gB = *(const float4*)(sG + kc * SG_RS + rdB);
            float2 g0 = make_float2(gA.x, gA.y);
            float2 g1 = make_float2(gA.z, gA.w);
            float2 g2 = make_float2(gB.x, gB.y);
            float2 g3 = make_float2(gB.z, gB.w);
            float ws[8] = {wA.x, wA.y, wA.z, wA.w, wB.x, wB.y, wB.z, wB.w};
            #pragma unroll
            for (int o = 0; o < 8; o++) {
                float2 w2 = make_float2(ws[o], ws[o]);
                acc[o][0] = ffma2(w2, g0, acc[o][0]);
                acc[o][1] = ffma2(w2, g1, acc[o][1]);
                acc[o][2] = ffma2(w2, g2, acc[o][2]);
                acc[o][3] = ffma2(w2, g3, acc[o][3]);
            }
        }
        // phase B reads only sG/sWo; next-iter sh writes are fenced by the
        // barrier at the top of the next iteration before phase A reads them.
    }

    // ---- store: thread's 8 px = one row segment of 8 cols ----
    const int orow = nj >> 2;
    const int ocol = (nj & 3) * 8;
    float* ob = out + (((size_t)b * 64 + mi * 8) * HW + y0 + orow) * HW + x0 + ocol;
    #pragma unroll
    for (int o = 0; o < 8; o++) {
        float4 v0 = make_float4(acc[o][0].x, acc[o][0].y, acc[o][1].x, acc[o][1].y);
        float4 v1 = make_float4(acc[o][2].x, acc[o][2].y, acc[o][3].x, acc[o][3].y);
        *(float4*)(ob + (size_t)o * HWHW)     = v0;
        *(float4*)(ob + (size_t)o * HWHW + 4) = v1;
    }
}

// ---------------------------------------------------------------------------
extern "C" void kernel_launch(void* const* d_in, const int* in_sizes, int n_in,
                              void* d_out, int out_size)
{
    const float* x     = (const float*)d_in[0];
    const float* W_in  = (const float*)d_in[1];
    const float* fftf  = (const float*)d_in[2];
    const float* W_dw  = (const float*)d_in[3];
    const float* W_out = (const float*)d_in[4];
    float* out = (float*)d_out;

    const int smem1 = (64 * 256 + HID * 4) * (int)sizeof(float);   // ~67 KB
    const int smem2 = (HID * 64 + 4 * 85 * 9 + 5 * SH_GRP + 10 * SG_RS) * (int)sizeof(float); // ~80 KB
    cudaFuncSetAttribute(pass1_kernel, cudaFuncAttributeMaxDynamicSharedMemorySize, smem1);
    cudaFuncSetAttribute(pass2_kernel, cudaFuncAttributeMaxDynamicSharedMemorySize, smem2);

    pass1_kernel<<<dim3(2, 128, 4), 256, smem1>>>(x, W_in, fftf);
    pass2_kernel<<<dim3(8, 32, 4), 256, smem2>>>(W_dw, W_out, out);
}